// round 7
// baseline (speedup 1.0000x reference)
#include <cuda_runtime.h>
#include <math.h>

#define Bq   8
#define Nq   1024
#define Hq   200
#define BNr  (Bq*Nq)
#define NCH  8
#define KCH  8

// ---------------- scratch (no allocs allowed) ----------------
__device__ float g_outs  [BNr*Hq];
__device__ float g_output[BNr*Hq];
__device__ float g_bufA  [BNr*Hq];
__device__ float g_bufB  [BNr*Hq];
__device__ float g_bufC  [BNr*Hq];
__device__ float g_scores[Bq*Nq*Nq];
__device__ float g_denom [BNr];
__device__ float g_rmax  [BNr];
__device__ float g_rsum  [BNr];
__device__ float g_cmax  [BNr];
__device__ float g_csum  [BNr];
__device__ float g_pmax  [NCH*BNr];
__device__ float g_psum  [NCH*BNr];

// ---------------- helpers ----------------
__device__ __forceinline__ float warp_red_sum(float v){
#pragma unroll
    for (int o=16;o;o>>=1) v += __shfl_xor_sync(0xffffffffu, v, o);
    return v;
}
__device__ __forceinline__ float warp_red_max(float v){
#pragma unroll
    for (int o=16;o;o>>=1) v = fmaxf(v, __shfl_xor_sync(0xffffffffu, v, o));
    return v;
}

// packed fp32x2 FMA (FFMA2) — only reachable via explicit PTX
__device__ __forceinline__ void ffma2(unsigned long long &d,
                                      unsigned long long a,
                                      unsigned long long b){
    asm("fma.rn.f32x2 %0, %1, %2, %0;" : "+l"(d) : "l"(a), "l"(b));
}
__device__ __forceinline__ void unpack2(unsigned long long v, float &lo, float &hi){
    asm("mov.b64 {%0, %1}, %2;" : "=f"(lo), "=f"(hi) : "l"(v));
}

// ---------------- unified tiled GEMM (128x128 tile, 8x8 micro, FFMA2, dup-B) ----------------
// C[b,i,j] = epi( sum_k Aelem(b,i,k) * Belem(b,k,j) )
// AM: 0 plain row-major A[b,i,k]; 1 expf(A[b,i,k]-st1[b*M+i]); 2 expf(A[b,k,i]-st1[b*M+i]) (transposed)
// BM: 0 row-major B[b,k,j]; 1 transposed B[b,j,k]
// EPI: 0 +bias(opt); 1 +bias+res; 2 gelu(+bias); 3 *scale+keymask; 4 +pairmask;
//      5 relu(acc/st1)+res; 6 acc/st2*tm+res
// Requires: M%128==0, Kd%KCH==0 (true at all call sites: M in {8192,1024}, Kd in {200,1024})
template<int AM,int BM,int EPI>
__global__ void __launch_bounds__(256,2)
gemm_k(const float* __restrict__ A, const float* __restrict__ Bm, float* __restrict__ C,
       int M, int Nc, int Kd, int lda, int ldb, int ldc,
       long sA_, long sB_, long sC_,
       const float* __restrict__ bias, const float* __restrict__ res,
       const float* __restrict__ st1,  const float* __restrict__ st2,
       const float* __restrict__ tm, float scale)
{
    __shared__ float shA [2][KCH][132];   // [buf][kk][row]
    __shared__ float shBd[2][KCH][260];   // [buf][kk][2*col] duplicated pairs
    const int b  = blockIdx.z;
    const int i0 = blockIdx.y*128, j0 = blockIdx.x*128;
    const int tid = threadIdx.x;
    const int tx = tid & 15, ty = tid >> 4;
    const int bM = b*M;
    const float* Ab = A + (long)b*sA_;
    const float* Bb = Bm + (long)b*sB_;

    unsigned long long acc[4][8];
#pragma unroll
    for (int p=0;p<4;p++)
#pragma unroll
        for (int j=0;j<8;j++) acc[p][j]=0ull;

    // register staging
    float4 ra4;             // AM 0/1 : row r0, k q*4..+3
    float  ra [4];          // AM 2
    float  rb [4];          // BM 0
    float4 rb4;             // BM 1

    const int q  = tid & 1,  r0 = tid >> 1;    // A (AM 0/1)
    const int cb0= tid & 127, kb = tid >> 7;   // B (BM 0)
    const int tk = (tid & 1)*4, cb1 = tid >> 1;// B (BM 1)

    auto loadA = [&](int k0){
        if (AM==2){
#pragma unroll
            for (int p=0;p<4;p++){
                int idx = p*256+tid; int row = idx&127, kk = idx>>7;
                ra[p] = __expf(Ab[(long)(k0+kk)*lda + (i0+row)] - st1[bM+i0+row]);
            }
        } else {
            ra4 = *(const float4*)&Ab[(long)(i0+r0)*lda + k0 + q*4];
            if (AM==1){
                float m = st1[bM+i0+r0];
                ra4.x=__expf(ra4.x-m); ra4.y=__expf(ra4.y-m);
                ra4.z=__expf(ra4.z-m); ra4.w=__expf(ra4.w-m);
            }
        }
    };
    auto storeA = [&](int sel){
        if (AM==2){
#pragma unroll
            for (int p=0;p<4;p++){
                int idx = p*256+tid;
                shA[sel][idx>>7][idx&127] = ra[p];
            }
        } else {
            shA[sel][q*4+0][r0]=ra4.x;
            shA[sel][q*4+1][r0]=ra4.y;
            shA[sel][q*4+2][r0]=ra4.z;
            shA[sel][q*4+3][r0]=ra4.w;
        }
    };
    auto loadB = [&](int k0){
        if (BM==0){
            int gj = j0 + cb0;
            bool ok = gj < Nc;
#pragma unroll
            for (int p=0;p<4;p++){
                int gk = k0 + kb*4 + p;
                rb[p] = ok ? Bb[(long)gk*ldb + gj] : 0.f;
            }
        } else {
            int gj = j0 + cb1;
            rb4 = (gj<Nc) ? *(const float4*)&Bb[(long)gj*ldb + k0 + tk]
                          : make_float4(0.f,0.f,0.f,0.f);
        }
    };
    auto storeB = [&](int sel){
        if (BM==0){
#pragma unroll
            for (int p=0;p<4;p++){
                float2 d = make_float2(rb[p], rb[p]);
                *(float2*)&shBd[sel][kb*4+p][2*cb0] = d;
            }
        } else {
            *(float2*)&shBd[sel][tk+0][2*cb1] = make_float2(rb4.x, rb4.x);
            *(float2*)&shBd[sel][tk+1][2*cb1] = make_float2(rb4.y, rb4.y);
            *(float2*)&shBd[sel][tk+2][2*cb1] = make_float2(rb4.z, rb4.z);
            *(float2*)&shBd[sel][tk+3][2*cb1] = make_float2(rb4.w, rb4.w);
        }
    };

    const int nch = Kd / KCH;
    loadA(0); loadB(0);
    int c = 0;
    while (true){
        int sel = c & 1;
        storeA(sel); storeB(sel);
        __syncthreads();
        ++c;
        bool more = c < nch;
        if (more){ loadA(c*KCH); loadB(c*KCH); }
#pragma unroll
        for (int kk=0;kk<KCH;kk++){
            ulonglong2 A0 = *(const ulonglong2*)&shA[sel][kk][ty*8];
            ulonglong2 A1 = *(const ulonglong2*)&shA[sel][kk][ty*8+4];
            ulonglong2 B0 = *(const ulonglong2*)&shBd[sel][kk][tx*16];
            ulonglong2 B1 = *(const ulonglong2*)&shBd[sel][kk][tx*16+4];
            ulonglong2 B2 = *(const ulonglong2*)&shBd[sel][kk][tx*16+8];
            ulonglong2 B3 = *(const ulonglong2*)&shBd[sel][kk][tx*16+12];
            unsigned long long bd[8] = {B0.x,B0.y,B1.x,B1.y,B2.x,B2.y,B3.x,B3.y};
            unsigned long long av[4] = {A0.x,A0.y,A1.x,A1.y};
#pragma unroll
            for (int p=0;p<4;p++)
#pragma unroll
                for (int j=0;j<8;j++)
                    ffma2(acc[p][j], av[p], bd[j]);
        }
        if (!more) break;
    }

    // ---- epilogue ----
#pragma unroll
    for (int p=0;p<4;p++){
        int gi0 = i0 + ty*8 + p*2;   // rows gi0, gi0+1
#pragma unroll
        for (int j=0;j<8;j++){
            int gj = j0 + tx*8 + j;
            if (gj>=Nc) continue;
            float v0, v1;
            unpack2(acc[p][j], v0, v1);
#pragma unroll
            for (int h=0; h<2; h++){
                int gi = gi0 + h;
                float v = h ? v1 : v0;
                long cidx = (long)b*sC_ + (long)gi*ldc + gj;
                if (EPI==0){ if (bias) v += bias[gj]; }
                else if (EPI==1){ v += bias[gj]; v += res[cidx]; }
                else if (EPI==2){ v += bias[gj]; v = 0.5f*v*(1.f+erff(v*0.70710678f)); }
                else if (EPI==3){ v = v*scale + (tm[b*Nq+gj]-1.f)*10000.f; }
                else if (EPI==4){ v = v + (tm[b*Nq+gi]*tm[b*Nq+gj]-1.f)*10000.f; }
                else if (EPI==5){ v = fmaxf(v/st1[bM+gi], 0.f) + res[cidx]; }
                else if (EPI==6){ v = v/st2[bM+gi]*tm[b*Nq+gi] + res[cidx]; }
                C[cidx] = v;
            }
        }
    }
}

// ---------------- softmax / stats ----------------
template<bool WRITE>
__global__ void __launch_bounds__(256)
softmax_row_k(float* __restrict__ S, float* __restrict__ rmax, float* __restrict__ rsum){
    long row = blockIdx.x;
    float* p = S + row*(long)Nq;
    int t = threadIdx.x;
    float v[4];
    float mx = -1e30f;
#pragma unroll
    for (int l=0;l<4;l++){ v[l]=p[t+l*256]; mx=fmaxf(mx,v[l]); }
    __shared__ float sm[8];
    mx = warp_red_max(mx);
    if ((t&31)==0) sm[t>>5]=mx;
    __syncthreads();
    float m2 = sm[0];
#pragma unroll
    for (int w=1;w<8;w++) m2 = fmaxf(m2, sm[w]);
    float s = 0.f;
#pragma unroll
    for (int l=0;l<4;l++){ v[l]=__expf(v[l]-m2); s+=v[l]; }
    __syncthreads();
    s = warp_red_sum(s);
    if ((t&31)==0) sm[t>>5]=s;
    __syncthreads();
    float st = 0.f;
#pragma unroll
    for (int w=0;w<8;w++) st += sm[w];
    if (WRITE){
        float inv = 1.f/st;
#pragma unroll
        for (int l=0;l<4;l++) p[t+l*256] = v[l]*inv;
    } else if (t==0){ rmax[row]=m2; rsum[row]=st; }
}

__global__ void __launch_bounds__(256)
colstats_part(const float* __restrict__ L, float* __restrict__ pmax, float* __restrict__ psum){
    int g  = blockIdx.x*256 + threadIdx.x;       // 0..BNr-1 : (b,m)
    int ch = blockIdx.y;
    int b = g >> 10, m = g & 1023;
    const float* p = L + (long)b*Nq*Nq + m + (long)ch*(Nq/NCH)*Nq;
    float mx=-1e30f, s=0.f;
#pragma unroll 4
    for (int n=0;n<Nq/NCH;n++){
        float x = p[(long)n*Nq];
        if (x>mx){ s = s*__expf(mx-x) + 1.f; mx = x; }
        else       s += __expf(x-mx);
    }
    pmax[ch*BNr+g]=mx; psum[ch*BNr+g]=s;
}
__global__ void __launch_bounds__(256)
colstats_comb(const float* __restrict__ pmax, const float* __restrict__ psum,
              float* __restrict__ cmax, float* __restrict__ csum){
    int g = blockIdx.x*256 + threadIdx.x;
    float mx=-1e30f, s=0.f;
#pragma unroll
    for (int ch=0; ch<NCH; ch++){
        float m2=pmax[ch*BNr+g], s2=psum[ch*BNr+g];
        if (m2>mx){ s = s*__expf(mx-m2) + s2; mx = m2; }
        else        s += s2*__expf(m2-mx);
    }
    cmax[g]=mx; csum[g]=s;
}

// ---------------- layernorm (1 warp / row, H=200) ----------------
__global__ void __launch_bounds__(32)
ln_k(const float* __restrict__ X, const float* __restrict__ g,
     const float* __restrict__ bt, float* __restrict__ Y){
    long row = blockIdx.x;
    const float* x = X + row*Hq;
    float* y = Y + row*Hq;
    int t = threadIdx.x;
    float v[7]; float s=0.f;
#pragma unroll
    for (int l=0;l<7;l++){ int c=t+l*32; v[l]=(c<Hq)?x[c]:0.f; s+=v[l]; }
    s = warp_red_sum(s);
    float mu = s*(1.f/Hq);
    float var = 0.f;
#pragma unroll
    for (int l=0;l<7;l++){ int c=t+l*32; if (c<Hq){ float d=v[l]-mu; var+=d*d; } }
    var = warp_red_sum(var)*(1.f/Hq);
    float r = rsqrtf(var + 1e-20f);
#pragma unroll
    for (int l=0;l<7;l++){ int c=t+l*32; if (c<Hq) y[c] = (v[l]-mu)*r*g[c]+bt[c]; }
}

// ---------------- adj + denom ----------------
__global__ void __launch_bounds__(256)
adj_k(const float* __restrict__ a1, const float* __restrict__ a2,
      float* __restrict__ adjo, float* __restrict__ den){
    long row = blockIdx.x;
    long base = row*(long)Nq;
    int t = threadIdx.x;
    float s = 0.f;
#pragma unroll
    for (int l=0;l<4;l++){
        int m = t+l*256;
        float v = fminf(a1[base+m]+a2[base+m], 1.f);
        adjo[base+m]=v; s+=v;
    }
    __shared__ float sm[8];
    s = warp_red_sum(s);
    if ((t&31)==0) sm[t>>5]=s;
    __syncthreads();
    if (t==0){
        float tot=0.f;
#pragma unroll
        for (int w=0;w<8;w++) tot+=sm[w];
        den[row]=tot+1e-7f;
    }
}

__global__ void init_k(const float* __restrict__ text, float* __restrict__ o1, float* __restrict__ o2){
    for (long i = blockIdx.x*256L + threadIdx.x; i < (long)BNr*Hq; i += (long)gridDim.x*256)
    { float v=text[i]; o1[i]=v; o2[i]=v; }
}

// ---------------- host-side GEMM launcher ----------------
template<int AM,int BM,int EPI>
static void G(const float*A,const float*Bm,float*C,int M,int Nc,int Kd,
              int lda,int ldb,int ldc,long sa,long sb,long sc,int batch,
              const float*bias,const float*res,const float*st1,const float*st2,
              const float*tmv,float scale){
    dim3 grid((Nc+127)/128, M/128, batch);
    gemm_k<AM,BM,EPI><<<grid,256>>>(A,Bm,C,M,Nc,Kd,lda,ldb,ldc,sa,sb,sc,bias,res,st1,st2,tmv,scale);
}

extern "C" void kernel_launch(void* const* d_in, const int* in_sizes, int n_in,
                              void* d_out, int out_size)
{
    const float* text  = (const float*)d_in[0];
    const float* adj1  = (const float*)d_in[1];
    const float* adj2  = (const float*)d_in[2];
    const float* tmask = (const float*)d_in[5];
    const float* gcn_w = (const float*)d_in[6];
    const float* mut_w = (const float*)d_in[7];
    const float* qw=(const float*)d_in[8],  *qb=(const float*)d_in[9];
    const float* kw=(const float*)d_in[10], *kb=(const float*)d_in[11];
    const float* vw=(const float*)d_in[12], *vb=(const float*)d_in[13];
    const float* aw=(const float*)d_in[14], *ab=(const float*)d_in[15];
    const float* g1=(const float*)d_in[16], *b1=(const float*)d_in[17];
    const float* iw=(const float*)d_in[18], *ib=(const float*)d_in[19];
    const float* ow=(const float*)d_in[20], *ob=(const float*)d_in[21];
    const float* g2=(const float*)d_in[22], *b2=(const float*)d_in[23];

    float* out  = (float*)d_out;
    float* adjo = out + (long)BNr*Hq;     // adj output region

    void* p;
    cudaGetSymbolAddress(&p, g_outs);   float* outs=(float*)p;
    cudaGetSymbolAddress(&p, g_output); float* outp=(float*)p;
    cudaGetSymbolAddress(&p, g_bufA);   float* bA=(float*)p;
    cudaGetSymbolAddress(&p, g_bufB);   float* bB=(float*)p;
    cudaGetSymbolAddress(&p, g_bufC);   float* bC=(float*)p;
    cudaGetSymbolAddress(&p, g_scores); float* sc=(float*)p;
    cudaGetSymbolAddress(&p, g_denom);  float* den=(float*)p;
    cudaGetSymbolAddress(&p, g_rmax);   float* rmax=(float*)p;
    cudaGetSymbolAddress(&p, g_rsum);   float* rsum=(float*)p;
    cudaGetSymbolAddress(&p, g_cmax);   float* cmax=(float*)p;
    cudaGetSymbolAddress(&p, g_csum);   float* csum=(float*)p;
    cudaGetSymbolAddress(&p, g_pmax);   float* pmax=(float*)p;
    cudaGetSymbolAddress(&p, g_psum);   float* psum=(float*)p;

    const long sNH = (long)Nq*Hq;
    const long sNN = (long)Nq*Nq;
    const float rscale = 1.0f/sqrtf((float)Hq);

    init_k<<<640,256>>>(text, outs, outp);
    adj_k<<<BNr,256>>>(adj1, adj2, adjo, den);

    for (int i=0;i<3;i++){
        const float *qwi=qw+i*Hq*Hq, *qbi=qb+i*Hq;
        const float *kwi=kw+i*Hq*Hq, *kbi=kb+i*Hq;
        const float *vwi=vw+i*Hq*Hq, *vbi=vb+i*Hq;
        const float *awi=aw+i*Hq*Hq, *abi=ab+i*Hq;
        const float *iwi=iw+i*Hq*Hq, *ibi=ib+i*Hq;
        const float *owi=ow+i*Hq*Hq, *obi=ob+i*Hq;
        const float *g1i=g1+i*Hq, *b1i=b1+i*Hq, *g2i=g2+i*Hq, *b2i=b2+i*Hq;

        // ---- BERT layer ----
        G<0,0,0>(outs,qwi,bA, BNr,Hq,Hq, Hq,Hq,Hq, 0,0,0, 1, qbi,0,0,0,0,0.f);     // q
        G<0,0,0>(outs,kwi,bB, BNr,Hq,Hq, Hq,Hq,Hq, 0,0,0, 1, kbi,0,0,0,0,0.f);     // k
        G<0,0,0>(outs,vwi,bC, BNr,Hq,Hq, Hq,Hq,Hq, 0,0,0, 1, vbi,0,0,0,0,0.f);     // v
        G<0,1,3>(bA,bB,sc, Nq,Nq,Hq, Hq,Hq,Nq, sNH,sNH,sNN, Bq, 0,0,0,0, tmask, rscale); // scores + keymask
        softmax_row_k<true><<<BNr,256>>>(sc, 0, 0);
        G<0,0,0>(sc,bC,bA, Nq,Hq,Nq, Nq,Hq,Hq, sNN,sNH,sNH, Bq, 0,0,0,0,0,0.f);    // ctx
        G<0,0,1>(bA,awi,bB, BNr,Hq,Hq, Hq,Hq,Hq, 0,0,0, 1, abi, outs, 0,0,0,0.f);  // pre-LN1
        ln_k<<<BNr,32>>>(bB, g1i, b1i, bC);                                         // attn
        G<0,0,2>(bC,iwi,bA, BNr,Hq,Hq, Hq,Hq,Hq, 0,0,0, 1, ibi,0,0,0,0,0.f);       // inter (gelu)
        G<0,0,1>(bA,owi,bB, BNr,Hq,Hq, Hq,Hq,Hq, 0,0,0, 1, obi, bC, 0,0,0,0.f);    // pre-LN2
        ln_k<<<BNr,32>>>(bB, g2i, b2i, outs);                                       // outs updated

        // ---- GCN propagation ----
        G<0,0,0>(outp,gcn_w,bA, BNr,Hq,Hq, Hq,Hq,Hq, 0,0,0, 1, 0,0,0,0,0,0.f);     // teout
        G<0,0,5>(adjo,bA,bB, Nq,Hq,Nq, Nq,Hq,Hq, sNN,sNH,sNH, Bq, 0, outp, den, 0, 0, 0.f);
        { float* t_=outp; outp=bB; bB=t_; }                                         // output <- new

        // ---- self-alignment ----
        G<0,0,0>(outs,mut_w,bA, BNr,Hq,Hq, Hq,Hq,Hq, 0,0,0, 1, 0,0,0,0,0,0.f);     // mo
        G<0,1,4>(bA,outp,sc, Nq,Nq,Hq, Hq,Hq,Nq, sNH,sNH,sNN, Bq, 0,0,0,0, tmask, 0.f); // logit + pairmask
        softmax_row_k<false><<<BNr,256>>>(sc, rmax, rsum);
        colstats_part<<<dim3(BNr/256,NCH),256>>>(sc, pmax, psum);
        colstats_comb<<<BNr/256,256>>>(pmax, psum, cmax, csum);
        G<1,0,6>(sc,outp,bC, Nq,Hq,Nq, Nq,Hq,Hq, sNN,sNH,sNH, Bq, 0, outs, rmax, rsum, tmask, 0.f); // new_outs
        G<2,0,6>(sc,outs,bB, Nq,Hq,Nq, Nq,Hq,Hq, sNN,sNH,sNH, Bq, 0, outp, cmax, csum, tmask, 0.f); // new_output
        { float* t_=outs; outs=bC; bC=t_; }
        { float* t_=outp; outp=bB; bB=t_; }
    }

    cudaMemcpyAsync(out, outs, (size_t)BNr*Hq*sizeof(float), cudaMemcpyDeviceToDevice);
}

// round 8
// speedup vs baseline: 2.1122x; 2.1122x over previous
#include <cuda_runtime.h>
#include <math.h>

#define Bq   8
#define Nq   1024
#define Hq   200
#define BNr  (Bq*Nq)
#define NCH  8
#define KCH  16

// ---------------- scratch (no allocs allowed) ----------------
__device__ float g_outs  [BNr*Hq];
__device__ float g_output[BNr*Hq];
__device__ float g_bufA  [BNr*Hq];
__device__ float g_bufB  [BNr*Hq];
__device__ float g_bufC  [BNr*Hq];
__device__ float g_scores[Bq*Nq*Nq];
__device__ float g_denom [BNr];
__device__ float g_rmax  [BNr];
__device__ float g_rsum  [BNr];
__device__ float g_cmax  [BNr];
__device__ float g_csum  [BNr];
__device__ float g_pmax  [NCH*BNr];
__device__ float g_psum  [NCH*BNr];

// ---------------- helpers ----------------
__device__ __forceinline__ float warp_red_sum(float v){
#pragma unroll
    for (int o=16;o;o>>=1) v += __shfl_xor_sync(0xffffffffu, v, o);
    return v;
}
__device__ __forceinline__ float warp_red_max(float v){
#pragma unroll
    for (int o=16;o;o>>=1) v = fmaxf(v, __shfl_xor_sync(0xffffffffu, v, o));
    return v;
}

// packed fp32x2 FMA (FFMA2) — only reachable via explicit PTX
__device__ __forceinline__ void ffma2(unsigned long long &d,
                                      unsigned long long a,
                                      unsigned long long b){
    asm("fma.rn.f32x2 %0, %1, %2, %0;" : "+l"(d) : "l"(a), "l"(b));
}
__device__ __forceinline__ void unpack2(unsigned long long v, float &lo, float &hi){
    asm("mov.b64 {%0, %1}, %2;" : "=f"(lo), "=f"(hi) : "l"(v));
}

// ---------------- unified tiled GEMM ----------------
// 128x64 CTA tile, 8 rows x 4 cols micro-tile as 8x2 packed col-pairs.
// A stored DUPLICATED in smem (broadcast reads -> free); B plain (natural pairs).
// Double-buffered smem, single __syncthreads per k-chunk.
// C[b,i,j] = epi( sum_k Aelem(b,i,k) * Belem(b,k,j) )
// AM: 0 plain row-major A[b,i,k]; 1 expf(A[b,i,k]-st1[b*M+i]); 2 expf(A[b,k,i]-st1[b*M+i]) (transposed)
// BM: 0 row-major B[b,k,j]; 1 transposed B[b,j,k]
// EPI: 0 +bias(opt); 1 +bias+res; 2 gelu(+bias); 3 *scale+keymask; 4 +pairmask;
//      5 relu(acc/st1)+res; 6 acc/st2*tm+res
// Requires: M % 128 == 0 (call sites: M in {8192, 1024})
template<int AM,int BM,int EPI>
__global__ void __launch_bounds__(256,2)
gemm_k(const float* __restrict__ A, const float* __restrict__ Bm, float* __restrict__ C,
       int M, int Nc, int Kd, int lda, int ldb, int ldc,
       long sA_, long sB_, long sC_,
       const float* __restrict__ bias, const float* __restrict__ res,
       const float* __restrict__ st1,  const float* __restrict__ st2,
       const float* __restrict__ tm, float scale)
{
    __shared__ __align__(16) float shAd[2][KCH][260];  // duplicated A pairs: col 2r,2r+1 = a[row r]
    __shared__ __align__(16) float shB [2][KCH][68];   // plain B
    const int b  = blockIdx.z;
    const int i0 = blockIdx.y*128, j0 = blockIdx.x*64;
    const int tid = threadIdx.x;
    const int tx = tid & 15, ty = tid >> 4;
    const int bM = b*M;
    const float* Ab = A + (long)b*sA_;
    const float* Bb = Bm + (long)b*sB_;

    unsigned long long acc[8][2];
#pragma unroll
    for (int r=0;r<8;r++){ acc[r][0]=0ull; acc[r][1]=0ull; }

    // register staging
    float4 ra4[2];          // AM 0/1 : rows r0, r0+64, k q*4..+3
    float  ra [8];          // AM 2
    float  rb [4];          // B

    const int q  = tid & 3,  r0 = tid >> 2;    // A (AM 0/1): 64 rows x 4 k-quads, x2
    const int cb0= tid & 63, kb = tid >> 6;    // B (BM 0)
    const int tk = tid & 15, cb1 = tid >> 4;   // B (BM 1)

    auto loadA = [&](int k0){
        if (AM==2){
#pragma unroll
            for (int p=0;p<8;p++){
                int idx = p*256+tid; int row = idx&127, kk = idx>>7;
                int gk = k0+kk;
                ra[p] = (gk<Kd) ? __expf(Ab[(long)gk*lda + (i0+row)] - st1[bM+i0+row]) : 0.f;
            }
        } else {
            int gk = k0 + q*4;
#pragma unroll
            for (int p=0;p<2;p++){
                int gi = i0 + p*64 + r0;
                float4 v = make_float4(0.f,0.f,0.f,0.f);
                if (gk+3 < Kd){
                    v = *(const float4*)&Ab[(long)gi*lda+gk];
                    if (AM==1){
                        float m = st1[bM+gi];
                        v.x=__expf(v.x-m); v.y=__expf(v.y-m);
                        v.z=__expf(v.z-m); v.w=__expf(v.w-m);
                    }
                }
                ra4[p]=v;
            }
        }
    };
    auto storeA = [&](int sel){
        if (AM==2){
#pragma unroll
            for (int p=0;p<8;p++){
                int idx = p*256+tid; int row = idx&127, kk = idx>>7;
                *(float2*)&shAd[sel][kk][2*row] = make_float2(ra[p], ra[p]);
            }
        } else {
#pragma unroll
            for (int p=0;p<2;p++){
                int row = p*64 + r0;
                *(float2*)&shAd[sel][q*4+0][2*row] = make_float2(ra4[p].x, ra4[p].x);
                *(float2*)&shAd[sel][q*4+1][2*row] = make_float2(ra4[p].y, ra4[p].y);
                *(float2*)&shAd[sel][q*4+2][2*row] = make_float2(ra4[p].z, ra4[p].z);
                *(float2*)&shAd[sel][q*4+3][2*row] = make_float2(ra4[p].w, ra4[p].w);
            }
        }
    };
    auto loadB = [&](int k0){
        if (BM==0){
            int gj = j0 + cb0;
            bool ok = gj < Nc;
#pragma unroll
            for (int p=0;p<4;p++){
                int gk = k0 + kb*4 + p;
                rb[p] = (ok && gk<Kd) ? Bb[(long)gk*ldb + gj] : 0.f;
            }
        } else {
            int gk = k0 + tk;
            bool ok = gk < Kd;
#pragma unroll
            for (int p=0;p<4;p++){
                int gj = j0 + p*16 + cb1;
                rb[p] = (ok && gj<Nc) ? Bb[(long)gj*ldb + gk] : 0.f;
            }
        }
    };
    auto storeB = [&](int sel){
        if (BM==0){
#pragma unroll
            for (int p=0;p<4;p++) shB[sel][kb*4+p][cb0] = rb[p];
        } else {
#pragma unroll
            for (int p=0;p<4;p++) shB[sel][tk][p*16+cb1] = rb[p];
        }
    };

    const int nch = (Kd + KCH - 1) / KCH;
    loadA(0); loadB(0);
    storeA(0); storeB(0);
    int c = 0;
    while (true){
        __syncthreads();
        int sel = c & 1;
        ++c;
        bool more = c < nch;
        if (more){ loadA(c*KCH); loadB(c*KCH); }
#pragma unroll
        for (int kk=0;kk<KCH;kk++){
            ulonglong2 A0 = *(const ulonglong2*)&shAd[sel][kk][ty*16];
            ulonglong2 A1 = *(const ulonglong2*)&shAd[sel][kk][ty*16+4];
            ulonglong2 A2 = *(const ulonglong2*)&shAd[sel][kk][ty*16+8];
            ulonglong2 A3 = *(const ulonglong2*)&shAd[sel][kk][ty*16+12];
            ulonglong2 Bv = *(const ulonglong2*)&shB[sel][kk][tx*4];
            ffma2(acc[0][0],A0.x,Bv.x); ffma2(acc[0][1],A0.x,Bv.y);
            ffma2(acc[1][0],A0.y,Bv.x); ffma2(acc[1][1],A0.y,Bv.y);
            ffma2(acc[2][0],A1.x,Bv.x); ffma2(acc[2][1],A1.x,Bv.y);
            ffma2(acc[3][0],A1.y,Bv.x); ffma2(acc[3][1],A1.y,Bv.y);
            ffma2(acc[4][0],A2.x,Bv.x); ffma2(acc[4][1],A2.x,Bv.y);
            ffma2(acc[5][0],A2.y,Bv.x); ffma2(acc[5][1],A2.y,Bv.y);
            ffma2(acc[6][0],A3.x,Bv.x); ffma2(acc[6][1],A3.x,Bv.y);
            ffma2(acc[7][0],A3.y,Bv.x); ffma2(acc[7][1],A3.y,Bv.y);
        }
        if (!more) break;
        storeA(c & 1); storeB(c & 1);
    }

    // ---- epilogue ----
#pragma unroll
    for (int r=0;r<8;r++){
        int gi = i0 + ty*8 + r;
#pragma unroll
        for (int jp=0;jp<2;jp++){
            float v0, v1;
            unpack2(acc[r][jp], v0, v1);
#pragma unroll
            for (int h=0; h<2; h++){
                int gj = j0 + tx*4 + jp*2 + h;
                if (gj>=Nc) continue;
                float v = h ? v1 : v0;
                long cidx = (long)b*sC_ + (long)gi*ldc + gj;
                if (EPI==0){ if (bias) v += bias[gj]; }
                else if (EPI==1){ v += bias[gj]; v += res[cidx]; }
                else if (EPI==2){ v += bias[gj]; v = 0.5f*v*(1.f+erff(v*0.70710678f)); }
                else if (EPI==3){ v = v*scale + (tm[b*Nq+gj]-1.f)*10000.f; }
                else if (EPI==4){ v = v + (tm[b*Nq+gi]*tm[b*Nq+gj]-1.f)*10000.f; }
                else if (EPI==5){ v = fmaxf(v/st1[bM+gi], 0.f) + res[cidx]; }
                else if (EPI==6){ v = v/st2[bM+gi]*tm[b*Nq+gi] + res[cidx]; }
                C[cidx] = v;
            }
        }
    }
}

// ---------------- softmax / stats ----------------
template<bool WRITE>
__global__ void __launch_bounds__(256)
softmax_row_k(float* __restrict__ S, float* __restrict__ rmax, float* __restrict__ rsum){
    long row = blockIdx.x;
    float* p = S + row*(long)Nq;
    int t = threadIdx.x;
    float v[4];
    float mx = -1e30f;
#pragma unroll
    for (int l=0;l<4;l++){ v[l]=p[t+l*256]; mx=fmaxf(mx,v[l]); }
    __shared__ float sm[8];
    mx = warp_red_max(mx);
    if ((t&31)==0) sm[t>>5]=mx;
    __syncthreads();
    float m2 = sm[0];
#pragma unroll
    for (int w=1;w<8;w++) m2 = fmaxf(m2, sm[w]);
    float s = 0.f;
#pragma unroll
    for (int l=0;l<4;l++){ v[l]=__expf(v[l]-m2); s+=v[l]; }
    __syncthreads();
    s = warp_red_sum(s);
    if ((t&31)==0) sm[t>>5]=s;
    __syncthreads();
    float st = 0.f;
#pragma unroll
    for (int w=0;w<8;w++) st += sm[w];
    if (WRITE){
        float inv = 1.f/st;
#pragma unroll
        for (int l=0;l<4;l++) p[t+l*256] = v[l]*inv;
    } else if (t==0){ rmax[row]=m2; rsum[row]=st; }
}

__global__ void __launch_bounds__(256)
colstats_part(const float* __restrict__ L, float* __restrict__ pmax, float* __restrict__ psum){
    int g  = blockIdx.x*256 + threadIdx.x;       // 0..BNr-1 : (b,m)
    int ch = blockIdx.y;
    int b = g >> 10, m = g & 1023;
    const float* p = L + (long)b*Nq*Nq + m + (long)ch*(Nq/NCH)*Nq;
    float mx=-1e30f, s=0.f;
#pragma unroll 4
    for (int n=0;n<Nq/NCH;n++){
        float x = p[(long)n*Nq];
        if (x>mx){ s = s*__expf(mx-x) + 1.f; mx = x; }
        else       s += __expf(x-mx);
    }
    pmax[ch*BNr+g]=mx; psum[ch*BNr+g]=s;
}
__global__ void __launch_bounds__(256)
colstats_comb(const float* __restrict__ pmax, const float* __restrict__ psum,
              float* __restrict__ cmax, float* __restrict__ csum){
    int g = blockIdx.x*256 + threadIdx.x;
    float mx=-1e30f, s=0.f;
#pragma unroll
    for (int ch=0; ch<NCH; ch++){
        float m2=pmax[ch*BNr+g], s2=psum[ch*BNr+g];
        if (m2>mx){ s = s*__expf(mx-m2) + s2; mx = m2; }
        else        s += s2*__expf(m2-mx);
    }
    cmax[g]=mx; csum[g]=s;
}

// ---------------- layernorm (1 warp / row, H=200) ----------------
__global__ void __launch_bounds__(32)
ln_k(const float* __restrict__ X, const float* __restrict__ g,
     const float* __restrict__ bt, float* __restrict__ Y){
    long row = blockIdx.x;
    const float* x = X + row*Hq;
    float* y = Y + row*Hq;
    int t = threadIdx.x;
    float v[7]; float s=0.f;
#pragma unroll
    for (int l=0;l<7;l++){ int c=t+l*32; v[l]=(c<Hq)?x[c]:0.f; s+=v[l]; }
    s = warp_red_sum(s);
    float mu = s*(1.f/Hq);
    float var = 0.f;
#pragma unroll
    for (int l=0;l<7;l++){ int c=t+l*32; if (c<Hq){ float d=v[l]-mu; var+=d*d; } }
    var = warp_red_sum(var)*(1.f/Hq);
    float r = rsqrtf(var + 1e-20f);
#pragma unroll
    for (int l=0;l<7;l++){ int c=t+l*32; if (c<Hq) y[c] = (v[l]-mu)*r*g[c]+bt[c]; }
}

// ---------------- adj + denom ----------------
__global__ void __launch_bounds__(256)
adj_k(const float* __restrict__ a1, const float* __restrict__ a2,
      float* __restrict__ adjo, float* __restrict__ den){
    long row = blockIdx.x;
    long base = row*(long)Nq;
    int t = threadIdx.x;
    float s = 0.f;
#pragma unroll
    for (int l=0;l<4;l++){
        int m = t+l*256;
        float v = fminf(a1[base+m]+a2[base+m], 1.f);
        adjo[base+m]=v; s+=v;
    }
    __shared__ float sm[8];
    s = warp_red_sum(s);
    if ((t&31)==0) sm[t>>5]=s;
    __syncthreads();
    if (t==0){
        float tot=0.f;
#pragma unroll
        for (int w=0;w<8;w++) tot+=sm[w];
        den[row]=tot+1e-7f;
    }
}

__global__ void init_k(const float* __restrict__ text, float* __restrict__ o1, float* __restrict__ o2){
    for (long i = blockIdx.x*256L + threadIdx.x; i < (long)BNr*Hq; i += (long)gridDim.x*256)
    { float v=text[i]; o1[i]=v; o2[i]=v; }
}

// ---------------- host-side GEMM launcher ----------------
template<int AM,int BM,int EPI>
static void G(const float*A,const float*Bm,float*C,int M,int Nc,int Kd,
              int lda,int ldb,int ldc,long sa,long sb,long sc,int batch,
              const float*bias,const float*res,const float*st1,const float*st2,
              const float*tmv,float scale){
    dim3 grid((Nc+63)/64, M/128, batch);
    gemm_k<AM,BM,EPI><<<grid,256>>>(A,Bm,C,M,Nc,Kd,lda,ldb,ldc,sa,sb,sc,bias,res,st1,st2,tmv,scale);
}

extern "C" void kernel_launch(void* const* d_in, const int* in_sizes, int n_in,
                              void* d_out, int out_size)
{
    const float* text  = (const float*)d_in[0];
    const float* adj1  = (const float*)d_in[1];
    const float* adj2  = (const float*)d_in[2];
    const float* tmask = (const float*)d_in[5];
    const float* gcn_w = (const float*)d_in[6];
    const float* mut_w = (const float*)d_in[7];
    const float* qw=(const float*)d_in[8],  *qb=(const float*)d_in[9];
    const float* kw=(const float*)d_in[10], *kb=(const float*)d_in[11];
    const float* vw=(const float*)d_in[12], *vb=(const float*)d_in[13];
    const float* aw=(const float*)d_in[14], *ab=(const float*)d_in[15];
    const float* g1=(const float*)d_in[16], *b1=(const float*)d_in[17];
    const float* iw=(const float*)d_in[18], *ib=(const float*)d_in[19];
    const float* ow=(const float*)d_in[20], *ob=(const float*)d_in[21];
    const float* g2=(const float*)d_in[22], *b2=(const float*)d_in[23];

    float* out  = (float*)d_out;
    float* adjo = out + (long)BNr*Hq;     // adj output region

    void* p;
    cudaGetSymbolAddress(&p, g_outs);   float* outs=(float*)p;
    cudaGetSymbolAddress(&p, g_output); float* outp=(float*)p;
    cudaGetSymbolAddress(&p, g_bufA);   float* bA=(float*)p;
    cudaGetSymbolAddress(&p, g_bufB);   float* bB=(float*)p;
    cudaGetSymbolAddress(&p, g_bufC);   float* bC=(float*)p;
    cudaGetSymbolAddress(&p, g_scores); float* sc=(float*)p;
    cudaGetSymbolAddress(&p, g_denom);  float* den=(float*)p;
    cudaGetSymbolAddress(&p, g_rmax);   float* rmax=(float*)p;
    cudaGetSymbolAddress(&p, g_rsum);   float* rsum=(float*)p;
    cudaGetSymbolAddress(&p, g_cmax);   float* cmax=(float*)p;
    cudaGetSymbolAddress(&p, g_csum);   float* csum=(float*)p;
    cudaGetSymbolAddress(&p, g_pmax);   float* pmax=(float*)p;
    cudaGetSymbolAddress(&p, g_psum);   float* psum=(float*)p;

    const long sNH = (long)Nq*Hq;
    const long sNN = (long)Nq*Nq;
    const float rscale = 1.0f/sqrtf((float)Hq);

    init_k<<<640,256>>>(text, outs, outp);
    adj_k<<<BNr,256>>>(adj1, adj2, adjo, den);

    for (int i=0;i<3;i++){
        const float *qwi=qw+i*Hq*Hq, *qbi=qb+i*Hq;
        const float *kwi=kw+i*Hq*Hq, *kbi=kb+i*Hq;
        const float *vwi=vw+i*Hq*Hq, *vbi=vb+i*Hq;
        const float *awi=aw+i*Hq*Hq, *abi=ab+i*Hq;
        const float *iwi=iw+i*Hq*Hq, *ibi=ib+i*Hq;
        const float *owi=ow+i*Hq*Hq, *obi=ob+i*Hq;
        const float *g1i=g1+i*Hq, *b1i=b1+i*Hq, *g2i=g2+i*Hq, *b2i=b2+i*Hq;

        // ---- BERT layer ----
        G<0,0,0>(outs,qwi,bA, BNr,Hq,Hq, Hq,Hq,Hq, 0,0,0, 1, qbi,0,0,0,0,0.f);     // q
        G<0,0,0>(outs,kwi,bB, BNr,Hq,Hq, Hq,Hq,Hq, 0,0,0, 1, kbi,0,0,0,0,0.f);     // k
        G<0,0,0>(outs,vwi,bC, BNr,Hq,Hq, Hq,Hq,Hq, 0,0,0, 1, vbi,0,0,0,0,0.f);     // v
        G<0,1,3>(bA,bB,sc, Nq,Nq,Hq, Hq,Hq,Nq, sNH,sNH,sNN, Bq, 0,0,0,0, tmask, rscale); // scores + keymask
        softmax_row_k<true><<<BNr,256>>>(sc, 0, 0);
        G<0,0,0>(sc,bC,bA, Nq,Hq,Nq, Nq,Hq,Hq, sNN,sNH,sNH, Bq, 0,0,0,0,0,0.f);    // ctx
        G<0,0,1>(bA,awi,bB, BNr,Hq,Hq, Hq,Hq,Hq, 0,0,0, 1, abi, outs, 0,0,0,0.f);  // pre-LN1
        ln_k<<<BNr,32>>>(bB, g1i, b1i, bC);                                         // attn
        G<0,0,2>(bC,iwi,bA, BNr,Hq,Hq, Hq,Hq,Hq, 0,0,0, 1, ibi,0,0,0,0,0.f);       // inter (gelu)
        G<0,0,1>(bA,owi,bB, BNr,Hq,Hq, Hq,Hq,Hq, 0,0,0, 1, obi, bC, 0,0,0,0.f);    // pre-LN2
        ln_k<<<BNr,32>>>(bB, g2i, b2i, outs);                                       // outs updated

        // ---- GCN propagation ----
        G<0,0,0>(outp,gcn_w,bA, BNr,Hq,Hq, Hq,Hq,Hq, 0,0,0, 1, 0,0,0,0,0,0.f);     // teout
        G<0,0,5>(adjo,bA,bB, Nq,Hq,Nq, Nq,Hq,Hq, sNN,sNH,sNH, Bq, 0, outp, den, 0, 0, 0.f);
        { float* t_=outp; outp=bB; bB=t_; }                                         // output <- new

        // ---- self-alignment ----
        G<0,0,0>(outs,mut_w,bA, BNr,Hq,Hq, Hq,Hq,Hq, 0,0,0, 1, 0,0,0,0,0,0.f);     // mo
        G<0,1,4>(bA,outp,sc, Nq,Nq,Hq, Hq,Hq,Nq, sNH,sNH,sNN, Bq, 0,0,0,0, tmask, 0.f); // logit + pairmask
        softmax_row_k<false><<<BNr,256>>>(sc, rmax, rsum);
        colstats_part<<<dim3(BNr/256,NCH),256>>>(sc, pmax, psum);
        colstats_comb<<<BNr/256,256>>>(pmax, psum, cmax, csum);
        G<1,0,6>(sc,outp,bC, Nq,Hq,Nq, Nq,Hq,Hq, sNN,sNH,sNH, Bq, 0, outs, rmax, rsum, tmask, 0.f); // new_outs
        G<2,0,6>(sc,outs,bB, Nq,Hq,Nq, Nq,Hq,Hq, sNN,sNH,sNH, Bq, 0, outp, cmax, csum, tmask, 0.f); // new_output
        { float* t_=outs; outs=bC; bC=t_; }
        { float* t_=outp; outp=bB; bB=t_; }
    }

    cudaMemcpyAsync(out, outs, (size_t)BNr*Hq*sizeof(float), cudaMemcpyDeviceToDevice);
}

// round 11
// speedup vs baseline: 3.4814x; 1.6483x over previous
#include <cuda_runtime.h>
#include <math.h>
#include <stdint.h>

#define Bq   8
#define Nq   1024
#define Hq   200
#define BNr  (Bq*Nq)
#define NCH  8

// ---------------- scratch (no allocs allowed) ----------------
__device__ float g_outs  [BNr*Hq];
__device__ float g_output[BNr*Hq];
__device__ float g_bufA  [BNr*Hq];
__device__ float g_bufB  [BNr*Hq];
__device__ float g_bufC  [BNr*Hq];
__device__ float g_scores[Bq*Nq*Nq];
__device__ float g_scT   [Bq*Nq*Nq];
__device__ float g_denom [BNr];
__device__ float g_rmax  [BNr];
__device__ float g_rsum  [BNr];
__device__ float g_cmax  [BNr];
__device__ float g_csum  [BNr];
__device__ float g_pmax  [NCH*BNr];
__device__ float g_psum  [NCH*BNr];

// ---------------- generic helpers ----------------
__device__ __forceinline__ float warp_red_sum(float v){
#pragma unroll
    for (int o=16;o;o>>=1) v += __shfl_xor_sync(0xffffffffu, v, o);
    return v;
}
__device__ __forceinline__ float warp_red_max(float v){
#pragma unroll
    for (int o=16;o;o>>=1) v = fmaxf(v, __shfl_xor_sync(0xffffffffu, v, o));
    return v;
}

// ---------------- tensor-core primitives (baseline PTX, no 'a' features) ----------------
__device__ __forceinline__ uint32_t s2u(const void* p){
    uint32_t a;
    asm("{ .reg .u64 t; cvta.to.shared.u64 t, %1; cvt.u32.u64 %0, t; }" : "=r"(a) : "l"(p));
    return a;
}
__device__ __forceinline__ float tf32r(float x){
    uint32_t u;
    asm("cvt.rna.tf32.f32 %0, %1;" : "=r"(u) : "f"(x));
    return __uint_as_float(u);
}
__device__ __forceinline__ void ldmx4(uint32_t &r0,uint32_t &r1,uint32_t &r2,uint32_t &r3,uint32_t addr){
    asm volatile("ldmatrix.sync.aligned.m8n8.x4.shared.b16 {%0,%1,%2,%3}, [%4];"
        : "=r"(r0),"=r"(r1),"=r"(r2),"=r"(r3) : "r"(addr));
}
__device__ __forceinline__ void mma8(float* d, const uint32_t* a, const uint32_t* b){
    asm volatile("mma.sync.aligned.m16n8k8.row.col.f32.tf32.tf32.f32 "
        "{%0,%1,%2,%3}, {%4,%5,%6,%7}, {%8,%9}, {%0,%1,%2,%3};"
        : "+f"(d[0]),"+f"(d[1]),"+f"(d[2]),"+f"(d[3])
        : "r"(a[0]),"r"(a[1]),"r"(a[2]),"r"(a[3]), "r"(b[0]),"r"(b[1]));
}
// swizzled word offset: row stride 32 floats, 16B-group XOR swizzle
__device__ __forceinline__ int swoff(int row, int kg){
    return row*32 + (((kg ^ (row&7) ^ ((row>>3)&7))&7)<<2);
}

// ---------------- mma.sync tf32x3 GEMM (error-compensated) ----------------
// C[b,i,j] = epi( sum_k A[b,i,k] * Bop[b,k,j] ), fp32-accurate via
//   A = Ahi + Alo (tf32 split), C += Ahi*Bhi + Ahi*Blo + Alo*Bhi
// BT: 0 = B stored [Kd, Nc] row-major (transpose during smem staging)
//     1 = B stored [Nc, Kd] row-major (native K-major)
// EPI: 0 +bias(opt); 1 +bias+res; 2 gelu(+bias); 3 *scale+keymask(tm[gj]);
//      4 +pairmask; 5 relu(acc/st1[gi])+res; 6 acc*tm[gi]+res
// Requires M%128==0, Kd%4==0, Nc%4==0, 16B-aligned float4 rows.
template<int BT,int EPI>
__global__ void __launch_bounds__(256,2)
mma_k(const float* __restrict__ A, const float* __restrict__ Bm, float* __restrict__ C,
      int M, int Nc, int Kd, int lda, int ldb, int ldc,
      long sA_, long sB_, long sC_,
      const float* __restrict__ bias, const float* __restrict__ res,
      const float* __restrict__ st1, const float* __restrict__ tm, float scale)
{
    __shared__ __align__(16) float sA[2][128*32];   // [hi|lo]
    __shared__ __align__(16) float sB[2][64*32];    // [hi|lo]
    const int b  = blockIdx.z;
    const int i0 = blockIdx.y*128, j0 = blockIdx.x*64;
    const int tid = threadIdx.x, lid = tid&31, wid = tid>>5;
    const int wm = wid&3, wn = wid>>2;
    const float* Ab = A + (long)b*sA_;
    const float* Bb = Bm + (long)b*sB_;

    float acc[2][4][4];
#pragma unroll
    for (int mt=0;mt<2;mt++)
#pragma unroll
        for (int nt=0;nt<4;nt++)
#pragma unroll
            for (int e=0;e<4;e++) acc[mt][nt][e]=0.f;

    float4 ra[4];      // A staging
    float4 rb1[2];     // B staging BT=1
    float4 rbt[2];     // B staging BT=0

    auto ldgA = [&](int k0){
#pragma unroll
        for (int p=0;p<4;p++){
            int s = tid + p*256; int row = s>>3, kq = s&7;
            int gk = k0 + kq*4;
            ra[p] = (gk+3 < Kd) ? *(const float4*)&Ab[(long)(i0+row)*lda + gk]
                                : make_float4(0.f,0.f,0.f,0.f);
        }
    };
    auto stsA = [&](){
#pragma unroll
        for (int p=0;p<4;p++){
            int s = tid + p*256; int row = s>>3, kq = s&7;
            int off = swoff(row,kq);
            float4 v = ra[p];
            float4 h, l;
            h.x=tf32r(v.x); h.y=tf32r(v.y); h.z=tf32r(v.z); h.w=tf32r(v.w);
            l.x=tf32r(v.x-h.x); l.y=tf32r(v.y-h.y); l.z=tf32r(v.z-h.z); l.w=tf32r(v.w-h.w);
            *(float4*)&sA[0][off] = h;
            *(float4*)&sA[1][off] = l;
        }
    };
    auto ldgB = [&](int k0){
        if (BT==1){
#pragma unroll
            for (int p=0;p<2;p++){
                int s = tid + p*256; int row = s>>3, kq = s&7;
                int gj = j0 + row, gk = k0 + kq*4;
                rb1[p] = (gj < Nc && gk+3 < Kd) ? *(const float4*)&Bb[(long)gj*ldb + gk]
                                                : make_float4(0.f,0.f,0.f,0.f);
            }
        } else {
            int n0 = (tid&7)*8, kk = tid>>3;
            int gk = k0 + kk;
            bool ko = gk < Kd;
            int gn = j0 + n0;
            rbt[0] = (ko && gn+3 < Nc) ? *(const float4*)&Bb[(long)gk*ldb + gn]
                                       : make_float4(0.f,0.f,0.f,0.f);
            rbt[1] = (ko && gn+7 < Nc) ? *(const float4*)&Bb[(long)gk*ldb + gn + 4]
                                       : make_float4(0.f,0.f,0.f,0.f);
        }
    };
    auto stsB = [&](){
        if (BT==1){
#pragma unroll
            for (int p=0;p<2;p++){
                int s = tid + p*256; int row = s>>3, kq = s&7;
                int off = swoff(row,kq);
                float4 v = rb1[p];
                float4 h, l;
                h.x=tf32r(v.x); h.y=tf32r(v.y); h.z=tf32r(v.z); h.w=tf32r(v.w);
                l.x=tf32r(v.x-h.x); l.y=tf32r(v.y-h.y); l.z=tf32r(v.z-h.z); l.w=tf32r(v.w-h.w);
                *(float4*)&sB[0][off] = h;
                *(float4*)&sB[1][off] = l;
            }
        } else {
            int n0 = (tid&7)*8, kk = tid>>3;
            const float* pv = (const float*)rbt;
#pragma unroll
            for (int i=0;i<8;i++){
                int n = n0 + i;
                int off = n*32 + ((((kk>>2) ^ (n&7) ^ ((n>>3)&7))&7)<<2) + (kk&3);
                float x = pv[i];
                float h = tf32r(x);
                sB[0][off] = h;
                sB[1][off] = tf32r(x - h);
            }
        }
    };

    // per-lane fragment address precompute
    int arow[2], aswz[2];
#pragma unroll
    for (int mt=0;mt<2;mt++){
        arow[mt] = wm*32 + mt*16 + (lid&7) + ((lid>>3)&1)*8;
        aswz[mt] = (arow[mt]&7) ^ ((arow[mt]>>3)&7);
    }
    const int akg = (lid>>4);            // 0/1 -> +4 cols
    int brow[2], bswz[2];
#pragma unroll
    for (int jp=0;jp<2;jp++){
        brow[jp] = wn*32 + jp*16 + ((lid>>4)&1)*8 + (lid&7);
        bswz[jp] = (brow[jp]&7) ^ ((brow[jp]>>3)&7);
    }
    const int bkg = (lid>>3)&1;
    const uint32_t aHi = s2u(&sA[0][0]), aLo = aHi + 128*32*4;
    const uint32_t bHi = s2u(&sB[0][0]), bLo = bHi + 64*32*4;

    const int nch = (Kd + 31) >> 5;
    ldgA(0); ldgB(0);
    for (int c=0; c<nch; c++){
        stsA(); stsB();
        __syncthreads();
        if (c+1 < nch){ ldgA((c+1)*32); ldgB((c+1)*32); }
#pragma unroll
        for (int ks=0; ks<4; ks++){
            const int kg0 = ks*2;
            uint32_t af[2][2][4], bf[2][2][4];   // [mt|jp][hi/lo][4]
#pragma unroll
            for (int mt=0;mt<2;mt++){
                uint32_t aoff = 4u*(uint32_t)(arow[mt]*32 + ((((kg0+akg) ^ aswz[mt])&7)<<2));
                ldmx4(af[mt][0][0],af[mt][0][1],af[mt][0][2],af[mt][0][3], aHi + aoff);
                ldmx4(af[mt][1][0],af[mt][1][1],af[mt][1][2],af[mt][1][3], aLo + aoff);
            }
#pragma unroll
            for (int jp=0;jp<2;jp++){
                uint32_t boff = 4u*(uint32_t)(brow[jp]*32 + ((((kg0+bkg) ^ bswz[jp])&7)<<2));
                ldmx4(bf[jp][0][0],bf[jp][0][1],bf[jp][0][2],bf[jp][0][3], bHi + boff);
                ldmx4(bf[jp][1][0],bf[jp][1][1],bf[jp][1][2],bf[jp][1][3], bLo + boff);
            }
#pragma unroll
            for (int mt=0;mt<2;mt++)
#pragma unroll
                for (int nt=0;nt<4;nt++){
                    float* d = acc[mt][nt];
                    const uint32_t* bh = &bf[nt>>1][0][(nt&1)*2];
                    const uint32_t* bl = &bf[nt>>1][1][(nt&1)*2];
                    mma8(d, af[mt][1], bh);   // lo*hi
                    mma8(d, af[mt][0], bl);   // hi*lo
                    mma8(d, af[mt][0], bh);   // hi*hi
                }
        }
        if (c+1 < nch) __syncthreads();
    }

    // ---- epilogue ----
#pragma unroll
    for (int mt=0;mt<2;mt++){
        int gmr = i0 + wm*32 + mt*16 + (lid>>2);
#pragma unroll
        for (int nt=0;nt<4;nt++){
            int gn0 = j0 + wn*32 + nt*8 + (lid&3)*2;
#pragma unroll
            for (int e=0;e<4;e++){
                int gi = gmr + (e>>1)*8;
                int gj = gn0 + (e&1);
                if (gj >= Nc) continue;
                float v = acc[mt][nt][e];
                long cidx = (long)b*sC_ + (long)gi*ldc + gj;
                if (EPI==0){ if (bias) v += bias[gj]; }
                else if (EPI==1){ v += bias[gj]; v += res[cidx]; }
                else if (EPI==2){ v += bias[gj]; v = 0.5f*v*(1.f+erff(v*0.70710678f)); }
                else if (EPI==3){ v = v*scale + (tm[b*Nq+gj]-1.f)*10000.f; }
                else if (EPI==4){ v = v + (tm[b*Nq+gi]*tm[b*Nq+gj]-1.f)*10000.f; }
                else if (EPI==5){ v = fmaxf(v/st1[b*M+gi], 0.f) + res[cidx]; }
                else if (EPI==6){ v = v*tm[b*Nq+gi] + res[cidx]; }
                C[cidx] = v;
            }
        }
    }
}

// ---------------- softmax / stats ----------------
template<bool WRITE>
__global__ void __launch_bounds__(256)
softmax_row_k(float* __restrict__ S, float* __restrict__ rmax, float* __restrict__ rsum){
    long row = blockIdx.x;
    float* p = S + row*(long)Nq;
    int t = threadIdx.x;
    float v[4];
    float mx = -1e30f;
#pragma unroll
    for (int l=0;l<4;l++){ v[l]=p[t+l*256]; mx=fmaxf(mx,v[l]); }
    __shared__ float sm[8];
    mx = warp_red_max(mx);
    if ((t&31)==0) sm[t>>5]=mx;
    __syncthreads();
    float m2 = sm[0];
#pragma unroll
    for (int w=1;w<8;w++) m2 = fmaxf(m2, sm[w]);
    float s = 0.f;
#pragma unroll
    for (int l=0;l<4;l++){ v[l]=__expf(v[l]-m2); s+=v[l]; }
    __syncthreads();
    s = warp_red_sum(s);
    if ((t&31)==0) sm[t>>5]=s;
    __syncthreads();
    float st = 0.f;
#pragma unroll
    for (int w=0;w<8;w++) st += sm[w];
    if (WRITE){
        float inv = 1.f/st;
#pragma unroll
        for (int l=0;l<4;l++) p[t+l*256] = v[l]*inv;
    } else if (t==0){ rmax[row]=m2; rsum[row]=st; }
}

__global__ void __launch_bounds__(256)
colstats_part(const float* __restrict__ L, float* __restrict__ pmax, float* __restrict__ psum){
    int g  = blockIdx.x*256 + threadIdx.x;
    int ch = blockIdx.y;
    int b = g >> 10, m = g & 1023;
    const float* p = L + (long)b*Nq*Nq + m + (long)ch*(Nq/NCH)*Nq;
    float mx=-1e30f, s=0.f;
#pragma unroll 4
    for (int n=0;n<Nq/NCH;n++){
        float x = p[(long)n*Nq];
        if (x>mx){ s = s*__expf(mx-x) + 1.f; mx = x; }
        else       s += __expf(x-mx);
    }
    pmax[ch*BNr+g]=mx; psum[ch*BNr+g]=s;
}
__global__ void __launch_bounds__(256)
colstats_comb(const float* __restrict__ pmax, const float* __restrict__ psum,
              float* __restrict__ cmax, float* __restrict__ csum){
    int g = blockIdx.x*256 + threadIdx.x;
    float mx=-1e30f, s=0.f;
#pragma unroll
    for (int ch=0; ch<NCH; ch++){
        float m2=pmax[ch*BNr+g], s2=psum[ch*BNr+g];
        if (m2>mx){ s = s*__expf(mx-m2) + s2; mx = m2; }
        else        s += s2*__expf(m2-mx);
    }
    cmax[g]=mx; csum[g]=s;
}

// ---------------- dual normalize: P_row in place, P_col^T transposed ----------------
__global__ void __launch_bounds__(256)
normalize_dual(float* __restrict__ L, float* __restrict__ LT,
               const float* __restrict__ rmax, const float* __restrict__ rsum,
               const float* __restrict__ cmax, const float* __restrict__ csum){
    __shared__ float sm[32][33];
    int b = blockIdx.z;
    int i0 = blockIdx.y*32, j0 = blockIdx.x*32;
    int tx = threadIdx.x & 31, ty = threadIdx.x >> 5;
    float* Lb  = L  + (long)b*Nq*Nq;
    float* LTb = LT + (long)b*Nq*Nq;
    int gb = b*Nq;
#pragma unroll
    for (int p=0;p<4;p++){
        int ti = ty + p*8;
        int gi = i0+ti, gj = j0+tx;
        float l = Lb[(long)gi*Nq + gj];
        Lb[(long)gi*Nq + gj] = __expf(l - rmax[gb+gi]) / rsum[gb+gi];
        sm[ti][tx] = __expf(l - cmax[gb+gj]) / csum[gb+gj];
    }
    __syncthreads();
#pragma unroll
    for (int p=0;p<4;p++){
        int tj = ty + p*8;
        LTb[(long)(j0+tj)*Nq + i0 + tx] = sm[tx][tj];
    }
}

// ---------------- layernorm (1 warp / row, H=200) ----------------
__global__ void __launch_bounds__(32)
ln_k(const float* __restrict__ X, const float* __restrict__ g,
     const float* __restrict__ bt, float* __restrict__ Y){
    long row = blockIdx.x;
    const float* x = X + row*Hq;
    float* y = Y + row*Hq;
    int t = threadIdx.x;
    float v[7]; float s=0.f;
#pragma unroll
    for (int l=0;l<7;l++){ int c=t+l*32; v[l]=(c<Hq)?x[c]:0.f; s+=v[l]; }
    s = warp_red_sum(s);
    float mu = s*(1.f/Hq);
    float var = 0.f;
#pragma unroll
    for (int l=0;l<7;l++){ int c=t+l*32; if (c<Hq){ float d=v[l]-mu; var+=d*d; } }
    var = warp_red_sum(var)*(1.f/Hq);
    float r = rsqrtf(var + 1e-20f);
#pragma unroll
    for (int l=0;l<7;l++){ int c=t+l*32; if (c<Hq) y[c] = (v[l]-mu)*r*g[c]+bt[c]; }
}

// ---------------- adj + denom ----------------
__global__ void __launch_bounds__(256)
adj_k(const float* __restrict__ a1, const float* __restrict__ a2,
      float* __restrict__ adjo, float* __restrict__ den){
    long row = blockIdx.x;
    long base = row*(long)Nq;
    int t = threadIdx.x;
    float s = 0.f;
#pragma unroll
    for (int l=0;l<4;l++){
        int m = t+l*256;
        float v = fminf(a1[base+m]+a2[base+m], 1.f);
        adjo[base+m]=v; s+=v;
    }
    __shared__ float sm[8];
    s = warp_red_sum(s);
    if ((t&31)==0) sm[t>>5]=s;
    __syncthreads();
    if (t==0){
        float tot=0.f;
#pragma unroll
        for (int w=0;w<8;w++) tot+=sm[w];
        den[row]=tot+1e-7f;
    }
}

__global__ void init_k(const float* __restrict__ text, float* __restrict__ o1, float* __restrict__ o2){
    for (long i = blockIdx.x*256L + threadIdx.x; i < (long)BNr*Hq; i += (long)gridDim.x*256)
    { float v=text[i]; o1[i]=v; o2[i]=v; }
}

// ---------------- host-side GEMM launcher ----------------
template<int BT,int EPI>
static void MG(const float*A,const float*Bm,float*C,int M,int Nc,int Kd,
               int lda,int ldb,int ldc,long sa,long sb,long sc_,int batch,
               const float*bias,const float*res,const float*st1,const float*tmv,float scale){
    dim3 grid((Nc+63)/64, M/128, batch);
    mma_k<BT,EPI><<<grid,256>>>(A,Bm,C,M,Nc,Kd,lda,ldb,ldc,sa,sb,sc_,bias,res,st1,tmv,scale);
}

extern "C" void kernel_launch(void* const* d_in, const int* in_sizes, int n_in,
                              void* d_out, int out_size)
{
    const float* text  = (const float*)d_in[0];
    const float* adj1  = (const float*)d_in[1];
    const float* adj2  = (const float*)d_in[2];
    const float* tmask = (const float*)d_in[5];
    const float* gcn_w = (const float*)d_in[6];
    const float* mut_w = (const float*)d_in[7];
    const float* qw=(const float*)d_in[8],  *qb=(const float*)d_in[9];
    const float* kw=(const float*)d_in[10], *kb=(const float*)d_in[11];
    const float* vw=(const float*)d_in[12], *vb=(const float*)d_in[13];
    const float* aw=(const float*)d_in[14], *ab=(const float*)d_in[15];
    const float* g1=(const float*)d_in[16], *b1=(const float*)d_in[17];
    const float* iw=(const float*)d_in[18], *ib=(const float*)d_in[19];
    const float* ow=(const float*)d_in[20], *ob=(const float*)d_in[21];
    const float* g2=(const float*)d_in[22], *b2=(const float*)d_in[23];

    float* out  = (float*)d_out;
    float* adjo = out + (long)BNr*Hq;     // adj output region

    void* p;
    cudaGetSymbolAddress(&p, g_outs);   float* outs=(float*)p;
    cudaGetSymbolAddress(&p, g_output); float* outp=(float*)p;
    cudaGetSymbolAddress(&p, g_bufA);   float* bA=(float*)p;
    cudaGetSymbolAddress(&p, g_bufB);   float* bB=(float*)p;
    cudaGetSymbolAddress(&p, g_bufC);   float* bC=(float*)p;
    cudaGetSymbolAddress(&p, g_scores); float* sc=(float*)p;
    cudaGetSymbolAddress(&p, g_scT);    float* scT=(float*)p;
    cudaGetSymbolAddress(&p, g_denom);  float* den=(float*)p;
    cudaGetSymbolAddress(&p, g_rmax);   float* rmax=(float*)p;
    cudaGetSymbolAddress(&p, g_rsum);   float* rsum=(float*)p;
    cudaGetSymbolAddress(&p, g_cmax);   float* cmax=(float*)p;
    cudaGetSymbolAddress(&p, g_csum);   float* csum=(float*)p;
    cudaGetSymbolAddress(&p, g_pmax);   float* pmax=(float*)p;
    cudaGetSymbolAddress(&p, g_psum);   float* psum=(float*)p;

    const long sNH = (long)Nq*Hq;
    const long sNN = (long)Nq*Nq;
    const float rscale = 1.0f/sqrtf((float)Hq);

    init_k<<<640,256>>>(text, outs, outp);
    adj_k<<<BNr,256>>>(adj1, adj2, adjo, den);

    for (int i=0;i<3;i++){
        const float *qwi=qw+i*Hq*Hq, *qbi=qb+i*Hq;
        const float *kwi=kw+i*Hq*Hq, *kbi=kb+i*Hq;
        const float *vwi=vw+i*Hq*Hq, *vbi=vb+i*Hq;
        const float *awi=aw+i*Hq*Hq, *abi=ab+i*Hq;
        const float *iwi=iw+i*Hq*Hq, *ibi=ib+i*Hq;
        const float *owi=ow+i*Hq*Hq, *obi=ob+i*Hq;
        const float *g1i=g1+i*Hq, *b1i=b1+i*Hq, *g2i=g2+i*Hq, *b2i=b2+i*Hq;

        // ---- BERT layer ----
        MG<0,0>(outs,qwi,bA, BNr,Hq,Hq, Hq,Hq,Hq, 0,0,0, 1, qbi,0,0,0,0.f);     // q
        MG<0,0>(outs,kwi,bB, BNr,Hq,Hq, Hq,Hq,Hq, 0,0,0, 1, kbi,0,0,0,0.f);     // k
        MG<0,0>(outs,vwi,bC, BNr,Hq,Hq, Hq,Hq,Hq, 0,0,0, 1, vbi,0,0,0,0.f);     // v
        MG<1,3>(bA,bB,sc, Nq,Nq,Hq, Hq,Hq,Nq, sNH,sNH,sNN, Bq, 0,0,0, tmask, rscale); // scores + keymask
        softmax_row_k<true><<<BNr,256>>>(sc, 0, 0);
        MG<0,0>(sc,bC,bA, Nq,Hq,Nq, Nq,Hq,Hq, sNN,sNH,sNH, Bq, 0,0,0,0,0.f);    // ctx
        MG<0,1>(bA,awi,bB, BNr,Hq,Hq, Hq,Hq,Hq, 0,0,0, 1, abi, outs, 0,0,0.f);  // pre-LN1
        ln_k<<<BNr,32>>>(bB, g1i, b1i, bC);                                      // attn
        MG<0,2>(bC,iwi,bA, BNr,Hq,Hq, Hq,Hq,Hq, 0,0,0, 1, ibi,0,0,0,0.f);       // inter (gelu)
        MG<0,1>(bA,owi,bB, BNr,Hq,Hq, Hq,Hq,Hq, 0,0,0, 1, obi, bC, 0,0,0.f);    // pre-LN2
        ln_k<<<BNr,32>>>(bB, g2i, b2i, outs);                                    // outs updated

        // ---- GCN propagation ----
        MG<0,0>(outp,gcn_w,bA, BNr,Hq,Hq, Hq,Hq,Hq, 0,0,0, 1, 0,0,0,0,0.f);     // teout
        MG<0,5>(adjo,bA,bB, Nq,Hq,Nq, Nq,Hq,Hq, sNN,sNH,sNH, Bq, 0, outp, den, 0, 0.f);
        { float* t_=outp; outp=bB; bB=t_; }                                      // output <- new

        // ---- self-alignment ----
        MG<0,0>(outs,mut_w,bA, BNr,Hq,Hq, Hq,Hq,Hq, 0,0,0, 1, 0,0,0,0,0.f);     // mo
        MG<1,4>(bA,outp,sc, Nq,Nq,Hq, Hq,Hq,Nq, sNH,sNH,sNN, Bq, 0,0,0, tmask, 0.f); // logit + pairmask
        softmax_row_k<false><<<BNr,256>>>(sc, rmax, rsum);
        colstats_part<<<dim3(BNr/256,NCH),256>>>(sc, pmax, psum);
        colstats_comb<<<BNr/256,256>>>(pmax, psum, cmax, csum);
        normalize_dual<<<dim3(Nq/32,Nq/32,Bq),256>>>(sc, scT, rmax, rsum, cmax, csum);
        MG<0,6>(sc, outp, bC, Nq,Hq,Nq, Nq,Hq,Hq, sNN,sNH,sNH, Bq, 0, outs, 0, tmask, 0.f); // new_outs
        MG<0,6>(scT, outs, bB, Nq,Hq,Nq, Nq,Hq,Hq, sNN,sNH,sNH, Bq, 0, outp, 0, tmask, 0.f); // new_output
        { float* t_=outs; outs=bC; bC=t_; }
        { float* t_=outp; outp=bB; bB=t_; }
    }

    cudaMemcpyAsync(out, outs, (size_t)BNr*Hq*sizeof(float), cudaMemcpyDeviceToDevice);
}

// round 12
// speedup vs baseline: 4.9141x; 1.4115x over previous
#include <cuda_runtime.h>
#include <math.h>
#include <stdint.h>

#define Bq   8
#define Nq   1024
#define Hq   200
#define BNr  (Bq*Nq)
#define NCH  8

// ---------------- scratch (no allocs allowed) ----------------
__device__ float g_outs  [BNr*Hq];
__device__ float g_output[BNr*Hq];
__device__ float g_bufA  [BNr*Hq];
__device__ float g_bufB  [BNr*Hq];
__device__ float g_bufC  [BNr*Hq];
__device__ float g_scores[Bq*Nq*Nq];
__device__ float g_scT   [Bq*Nq*Nq];
__device__ float g_denom [BNr];
__device__ float g_rmax  [BNr];
__device__ float g_rsum  [BNr];
__device__ float g_cmax  [BNr];
__device__ float g_csum  [BNr];
__device__ float g_pmax  [NCH*BNr];
__device__ float g_psum  [NCH*BNr];

// ---------------- generic helpers ----------------
__device__ __forceinline__ float warp_red_sum(float v){
#pragma unroll
    for (int o=16;o;o>>=1) v += __shfl_xor_sync(0xffffffffu, v, o);
    return v;
}
__device__ __forceinline__ float warp_red_max(float v){
#pragma unroll
    for (int o=16;o;o>>=1) v = fmaxf(v, __shfl_xor_sync(0xffffffffu, v, o));
    return v;
}

// ---------------- tensor-core primitives (baseline PTX, no 'a' features) ----------------
__device__ __forceinline__ uint32_t s2u(const void* p){
    uint32_t a;
    asm("{ .reg .u64 t; cvta.to.shared.u64 t, %1; cvt.u32.u64 %0, t; }" : "=r"(a) : "l"(p));
    return a;
}
// pack two fp32 -> bf16x2 word: low half = bf16(x0), high half = bf16(x1)
__device__ __forceinline__ uint32_t bfp(float x0, float x1){
    uint32_t r;
    asm("cvt.rn.bf16x2.f32 %0, %1, %2;" : "=r"(r) : "f"(x1), "f"(x0));
    return r;
}
__device__ __forceinline__ float blo(uint32_t h){ return __uint_as_float(h<<16); }
__device__ __forceinline__ float bhi(uint32_t h){ return __uint_as_float(h & 0xFFFF0000u); }
__device__ __forceinline__ uint16_t bf1(float x){
    uint16_t r;
    asm("cvt.rn.bf16.f32 %0, %1;" : "=h"(r) : "f"(x));
    return r;
}
__device__ __forceinline__ void ldmx4(uint32_t* r, uint32_t addr){
    asm volatile("ldmatrix.sync.aligned.m8n8.x4.shared.b16 {%0,%1,%2,%3}, [%4];"
        : "=r"(r[0]),"=r"(r[1]),"=r"(r[2]),"=r"(r[3]) : "r"(addr));
}
__device__ __forceinline__ void mma16(float* d, const uint32_t* a, const uint32_t* b){
    asm volatile("mma.sync.aligned.m16n8k16.row.col.f32.bf16.bf16.f32 "
        "{%0,%1,%2,%3}, {%4,%5,%6,%7}, {%8,%9}, {%0,%1,%2,%3};"
        : "+f"(d[0]),"+f"(d[1]),"+f"(d[2]),"+f"(d[3])
        : "r"(a[0]),"r"(a[1]),"r"(a[2]),"r"(a[3]), "r"(b[0]),"r"(b[1]));
}
// 16B-group swizzle for 64B-row bf16 planes (4 groups/row)
__device__ __forceinline__ int swz4(int row){ return ((row>>1) ^ (row>>3)) & 3; }

// ---------------- mma.sync bf16x3 GEMM (error-compensated) ----------------
// C[b,i,j] = epi( sum_k A[b,i,k] * Bop[b,k,j] ), near-fp32 via
//   x = xh + xl (bf16 split), C += Ah*Bh + Ah*Bl + Al*Bh  (drop Al*Bl ~2^-16)
// BT: 0 = B stored [Kd, Nc] row-major (transpose during smem staging)
//     1 = B stored [Nc, Kd] row-major (native K-major)
// EPI: 0 +bias(opt); 1 +bias+res; 2 gelu(+bias); 3 *scale+keymask(tm[gj]);
//      4 +pairmask; 5 relu(acc/st1[gi])+res; 6 acc*tm[gi]+res
// Requires M%128==0, Kd%4==0, Nc%4==0, 16B-aligned float4 rows.
template<int BT,int EPI>
__global__ void __launch_bounds__(256,2)
mma_k(const float* __restrict__ A, const float* __restrict__ Bm, float* __restrict__ C,
      int M, int Nc, int Kd, int lda, int ldb, int ldc,
      long sA_, long sB_, long sC_,
      const float* __restrict__ bias, const float* __restrict__ res,
      const float* __restrict__ st1, const float* __restrict__ tm, float scale)
{
    // bf16 planes: [buf][plane hi/lo][row*64B], K-chunk = 32 bf16 per row
    __shared__ __align__(16) char sAm[2][2][128*64];   // 32 KB
    __shared__ __align__(16) char sBm[2][2][64*64];    // 16 KB
    const int b  = blockIdx.z;
    const int i0 = blockIdx.y*128, j0 = blockIdx.x*64;
    const int tid = threadIdx.x, lid = tid&31, wid = tid>>5;
    const int wm = wid&3, wn = wid>>2;
    const float* Ab = A + (long)b*sA_;
    const float* Bb = Bm + (long)b*sB_;

    float acc[2][4][4];
#pragma unroll
    for (int mt=0;mt<2;mt++)
#pragma unroll
        for (int nt=0;nt<4;nt++)
#pragma unroll
            for (int e=0;e<4;e++) acc[mt][nt][e]=0.f;

    float4 ra[4];      // A staging: 128 rows x 32 k / 256 thr
    float4 rb1[2];     // B staging BT=1
    float4 rbt[2];     // B staging BT=0

    auto ldgA = [&](int k0){
#pragma unroll
        for (int p=0;p<4;p++){
            int s = tid + p*256; int row = s>>3, kq = s&7;
            int gk = k0 + kq*4;
            ra[p] = (gk+3 < Kd) ? *(const float4*)&Ab[(long)(i0+row)*lda + gk]
                                : make_float4(0.f,0.f,0.f,0.f);
        }
    };
    auto stsA = [&](int sel){
#pragma unroll
        for (int p=0;p<4;p++){
            int s = tid + p*256; int row = s>>3, kq = s&7;
            float4 v = ra[p];
            uint32_t h0 = bfp(v.x, v.y), h1 = bfp(v.z, v.w);
            uint32_t l0 = bfp(v.x - blo(h0), v.y - bhi(h0));
            uint32_t l1 = bfp(v.z - blo(h1), v.w - bhi(h1));
            int off = row*64 + ((((kq>>1) ^ swz4(row))&3)<<4) + (kq&1)*8;
            *(uint2*)(sAm[sel][0] + off) = make_uint2(h0, h1);
            *(uint2*)(sAm[sel][1] + off) = make_uint2(l0, l1);
        }
    };
    auto ldgB = [&](int k0){
        if (BT==1){
#pragma unroll
            for (int p=0;p<2;p++){
                int s = tid + p*256; int row = s>>3, kq = s&7;
                int gj = j0 + row, gk = k0 + kq*4;
                rb1[p] = (gj < Nc && gk+3 < Kd) ? *(const float4*)&Bb[(long)gj*ldb + gk]
                                                : make_float4(0.f,0.f,0.f,0.f);
            }
        } else {
            int n0 = (tid&7)*8, kk = tid>>3;
            int gk = k0 + kk;
            bool ko = gk < Kd;
            int gn = j0 + n0;
            rbt[0] = (ko && gn+3 < Nc) ? *(const float4*)&Bb[(long)gk*ldb + gn]
                                       : make_float4(0.f,0.f,0.f,0.f);
            rbt[1] = (ko && gn+7 < Nc) ? *(const float4*)&Bb[(long)gk*ldb + gn + 4]
                                       : make_float4(0.f,0.f,0.f,0.f);
        }
    };
    auto stsB = [&](int sel){
        if (BT==1){
#pragma unroll
            for (int p=0;p<2;p++){
                int s = tid + p*256; int row = s>>3, kq = s&7;
                float4 v = rb1[p];
                uint32_t h0 = bfp(v.x, v.y), h1 = bfp(v.z, v.w);
                uint32_t l0 = bfp(v.x - blo(h0), v.y - bhi(h0));
                uint32_t l1 = bfp(v.z - blo(h1), v.w - bhi(h1));
                int off = row*64 + ((((kq>>1) ^ swz4(row))&3)<<4) + (kq&1)*8;
                *(uint2*)(sBm[sel][0] + off) = make_uint2(h0, h1);
                *(uint2*)(sBm[sel][1] + off) = make_uint2(l0, l1);
            }
        } else {
            int n0 = (tid&7)*8, kk = tid>>3;   // kk in 0..31
            const float* pv = (const float*)rbt;
            int gbyte = ((kk*2)>>4);           // 16B group within row
            int ibyte = (kk*2)&15;
#pragma unroll
            for (int i=0;i<8;i++){
                int n = n0 + i;
                float x = pv[i];
                uint16_t h = bf1(x);
                float hf = __uint_as_float(((uint32_t)h)<<16);
                uint16_t l = bf1(x - hf);
                int off = n*64 + (((gbyte ^ swz4(n))&3)<<4) + ibyte;
                *(uint16_t*)(sBm[sel][0] + off) = h;
                *(uint16_t*)(sBm[sel][1] + off) = l;
            }
        }
    };

    // per-lane fragment constants
    int arow[2], aswz[2];
#pragma unroll
    for (int mt=0;mt<2;mt++){
        arow[mt] = wm*32 + mt*16 + (lid&7) + ((lid>>3)&1)*8;
        aswz[mt] = swz4(arow[mt]);
    }
    const int akg = (lid>>4);          // 0/1: k-group within k16 step
    int brow[2], bswz[2];
#pragma unroll
    for (int jp=0;jp<2;jp++){
        brow[jp] = wn*32 + jp*16 + ((lid>>4)&1)*8 + (lid&7);
        bswz[jp] = swz4(brow[jp]);
    }
    const int bkg = (lid>>3)&1;
    uint32_t aB[2][2], bB[2][2];
#pragma unroll
    for (int s=0;s<2;s++)
#pragma unroll
        for (int pl=0;pl<2;pl++){
            aB[s][pl] = s2u(sAm[s][pl]);
            bB[s][pl] = s2u(sBm[s][pl]);
        }

    const int nch = (Kd + 31) >> 5;
    ldgA(0); ldgB(0);
    stsA(0); stsB(0);
    for (int c=0; c<nch; c++){
        __syncthreads();
        if (c+1 < nch){ ldgA((c+1)*32); ldgB((c+1)*32); }
        const int sel = c & 1;
#pragma unroll
        for (int ks=0; ks<2; ks++){
            uint32_t af[2][2][4], bf[2][2][4];   // [mt|jp][hi/lo][4]
#pragma unroll
            for (int mt=0;mt<2;mt++){
                uint32_t aoff = (uint32_t)(arow[mt]*64 + ((((2*ks+akg) ^ aswz[mt])&3)<<4));
                ldmx4(af[mt][0], aB[sel][0] + aoff);
                ldmx4(af[mt][1], aB[sel][1] + aoff);
            }
#pragma unroll
            for (int jp=0;jp<2;jp++){
                uint32_t boff = (uint32_t)(brow[jp]*64 + ((((2*ks+bkg) ^ bswz[jp])&3)<<4));
                ldmx4(bf[jp][0], bB[sel][0] + boff);
                ldmx4(bf[jp][1], bB[sel][1] + boff);
            }
#pragma unroll
            for (int mt=0;mt<2;mt++)
#pragma unroll
                for (int nt=0;nt<4;nt++){
                    float* d = acc[mt][nt];
                    const uint32_t* bh = &bf[nt>>1][0][(nt&1)*2];
                    const uint32_t* bl = &bf[nt>>1][1][(nt&1)*2];
                    mma16(d, af[mt][1], bh);   // lo*hi
                    mma16(d, af[mt][0], bl);   // hi*lo
                    mma16(d, af[mt][0], bh);   // hi*hi
                }
        }
        if (c+1 < nch){ stsA((c+1)&1); stsB((c+1)&1); }
    }

    // ---- epilogue ----
#pragma unroll
    for (int mt=0;mt<2;mt++){
        int gmr = i0 + wm*32 + mt*16 + (lid>>2);
#pragma unroll
        for (int nt=0;nt<4;nt++){
            int gn0 = j0 + wn*32 + nt*8 + (lid&3)*2;
#pragma unroll
            for (int e=0;e<4;e++){
                int gi = gmr + (e>>1)*8;
                int gj = gn0 + (e&1);
                if (gj >= Nc) continue;
                float v = acc[mt][nt][e];
                long cidx = (long)b*sC_ + (long)gi*ldc + gj;
                if (EPI==0){ if (bias) v += bias[gj]; }
                else if (EPI==1){ v += bias[gj]; v += res[cidx]; }
                else if (EPI==2){ v += bias[gj]; v = 0.5f*v*(1.f+erff(v*0.70710678f)); }
                else if (EPI==3){ v = v*scale + (tm[b*Nq+gj]-1.f)*10000.f; }
                else if (EPI==4){ v = v + (tm[b*Nq+gi]*tm[b*Nq+gj]-1.f)*10000.f; }
                else if (EPI==5){ v = fmaxf(v/st1[b*M+gi], 0.f) + res[cidx]; }
                else if (EPI==6){ v = v*tm[b*Nq+gi] + res[cidx]; }
                C[cidx] = v;
            }
        }
    }
}

// ---------------- softmax / stats ----------------
template<bool WRITE>
__global__ void __launch_bounds__(256)
softmax_row_k(float* __restrict__ S, float* __restrict__ rmax, float* __restrict__ rsum){
    long row = blockIdx.x;
    float* p = S + row*(long)Nq;
    int t = threadIdx.x;
    float v[4];
    float mx = -1e30f;
#pragma unroll
    for (int l=0;l<4;l++){ v[l]=p[t+l*256]; mx=fmaxf(mx,v[l]); }
    __shared__ float sm[8];
    mx = warp_red_max(mx);
    if ((t&31)==0) sm[t>>5]=mx;
    __syncthreads();
    float m2 = sm[0];
#pragma unroll
    for (int w=1;w<8;w++) m2 = fmaxf(m2, sm[w]);
    float s = 0.f;
#pragma unroll
    for (int l=0;l<4;l++){ v[l]=__expf(v[l]-m2); s+=v[l]; }
    __syncthreads();
    s = warp_red_sum(s);
    if ((t&31)==0) sm[t>>5]=s;
    __syncthreads();
    float st = 0.f;
#pragma unroll
    for (int w=0;w<8;w++) st += sm[w];
    if (WRITE){
        float inv = 1.f/st;
#pragma unroll
        for (int l=0;l<4;l++) p[t+l*256] = v[l]*inv;
    } else if (t==0){ rmax[row]=m2; rsum[row]=st; }
}

__global__ void __launch_bounds__(256)
colstats_part(const float* __restrict__ L, float* __restrict__ pmax, float* __restrict__ psum){
    int g  = blockIdx.x*256 + threadIdx.x;
    int ch = blockIdx.y;
    int b = g >> 10, m = g & 1023;
    const float* p = L + (long)b*Nq*Nq + m + (long)ch*(Nq/NCH)*Nq;
    float mx=-1e30f, s=0.f;
#pragma unroll 4
    for (int n=0;n<Nq/NCH;n++){
        float x = p[(long)n*Nq];
        if (x>mx){ s = s*__expf(mx-x) + 1.f; mx = x; }
        else       s += __expf(x-mx);
    }
    pmax[ch*BNr+g]=mx; psum[ch*BNr+g]=s;
}
__global__ void __launch_bounds__(256)
colstats_comb(const float* __restrict__ pmax, const float* __restrict__ psum,
              float* __restrict__ cmax, float* __restrict__ csum){
    int g = blockIdx.x*256 + threadIdx.x;
    float mx=-1e30f, s=0.f;
#pragma unroll
    for (int ch=0; ch<NCH; ch++){
        float m2=pmax[ch*BNr+g], s2=psum[ch*BNr+g];
        if (m2>mx){ s = s*__expf(mx-m2) + s2; mx = m2; }
        else        s += s2*__expf(m2-mx);
    }
    cmax[g]=mx; csum[g]=s;
}

// ---------------- dual normalize: P_row in place, P_col^T transposed ----------------
__global__ void __launch_bounds__(256)
normalize_dual(float* __restrict__ L, float* __restrict__ LT,
               const float* __restrict__ rmax, const float* __restrict__ rsum,
               const float* __restrict__ cmax, const float* __restrict__ csum){
    __shared__ float sm[32][33];
    int b = blockIdx.z;
    int i0 = blockIdx.y*32, j0 = blockIdx.x*32;
    int tx = threadIdx.x & 31, ty = threadIdx.x >> 5;
    float* Lb  = L  + (long)b*Nq*Nq;
    float* LTb = LT + (long)b*Nq*Nq;
    int gb = b*Nq;
#pragma unroll
    for (int p=0;p<4;p++){
        int ti = ty + p*8;
        int gi = i0+ti, gj = j0+tx;
        float l = Lb[(long)gi*Nq + gj];
        Lb[(long)gi*Nq + gj] = __expf(l - rmax[gb+gi]) / rsum[gb+gi];
        sm[ti][tx] = __expf(l - cmax[gb+gj]) / csum[gb+gj];
    }
    __syncthreads();
#pragma unroll
    for (int p=0;p<4;p++){
        int tj = ty + p*8;
        LTb[(long)(j0+tj)*Nq + i0 + tx] = sm[tx][tj];
    }
}

// ---------------- layernorm (1 warp / row, H=200) ----------------
__global__ void __launch_bounds__(32)
ln_k(const float* __restrict__ X, const float* __restrict__ g,
     const float* __restrict__ bt, float* __restrict__ Y){
    long row = blockIdx.x;
    const float* x = X + row*Hq;
    float* y = Y + row*Hq;
    int t = threadIdx.x;
    float v[7]; float s=0.f;
#pragma unroll
    for (int l=0;l<7;l++){ int c=t+l*32; v[l]=(c<Hq)?x[c]:0.f; s+=v[l]; }
    s = warp_red_sum(s);
    float mu = s*(1.f/Hq);
    float var = 0.f;
#pragma unroll
    for (int l=0;l<7;l++){ int c=t+l*32; if (c<Hq){ float d=v[l]-mu; var+=d*d; } }
    var = warp_red_sum(var)*(1.f/Hq);
    float r = rsqrtf(var + 1e-20f);
#pragma unroll
    for (int l=0;l<7;l++){ int c=t+l*32; if (c<Hq) y[c] = (v[l]-mu)*r*g[c]+bt[c]; }
}

// ---------------- adj + denom ----------------
__global__ void __launch_bounds__(256)
adj_k(const float* __restrict__ a1, const float* __restrict__ a2,
      float* __restrict__ adjo, float* __restrict__ den){
    long row = blockIdx.x;
    long base = row*(long)Nq;
    int t = threadIdx.x;
    float s = 0.f;
#pragma unroll
    for (int l=0;l<4;l++){
        int m = t+l*256;
        float v = fminf(a1[base+m]+a2[base+m], 1.f);
        adjo[base+m]=v; s+=v;
    }
    __shared__ float sm[8];
    s = warp_red_sum(s);
    if ((t&31)==0) sm[t>>5]=s;
    __syncthreads();
    if (t==0){
        float tot=0.f;
#pragma unroll
        for (int w=0;w<8;w++) tot+=sm[w];
        den[row]=tot+1e-7f;
    }
}

__global__ void init_k(const float* __restrict__ text, float* __restrict__ o1, float* __restrict__ o2){
    for (long i = blockIdx.x*256L + threadIdx.x; i < (long)BNr*Hq; i += (long)gridDim.x*256)
    { float v=text[i]; o1[i]=v; o2[i]=v; }
}

// ---------------- host-side GEMM launcher ----------------
template<int BT,int EPI>
static void MG(const float*A,const float*Bm,float*C,int M,int Nc,int Kd,
               int lda,int ldb,int ldc,long sa,long sb,long sc_,int batch,
               const float*bias,const float*res,const float*st1,const float*tmv,float scale){
    dim3 grid((Nc+63)/64, M/128, batch);
    mma_k<BT,EPI><<<grid,256>>>(A,Bm,C,M,Nc,Kd,lda,ldb,ldc,sa,sb,sc_,bias,res,st1,tmv,scale);
}

extern "C" void kernel_launch(void* const* d_in, const int* in_sizes, int n_in,
                              void* d_out, int out_size)
{
    const float* text  = (const float*)d_in[0];
    const float* adj1  = (const float*)d_in[1];
    const float* adj2  = (const float*)d_in[2];
    const float* tmask = (const float*)d_in[5];
    const float* gcn_w = (const float*)d_in[6];
    const float* mut_w = (const float*)d_in[7];
    const float* qw=(const float*)d_in[8],  *qb=(const float*)d_in[9];
    const float* kw=(const float*)d_in[10], *kb=(const float*)d_in[11];
    const float* vw=(const float*)d_in[12], *vb=(const float*)d_in[13];
    const float* aw=(const float*)d_in[14], *ab=(const float*)d_in[15];
    const float* g1=(const float*)d_in[16], *b1=(const float*)d_in[17];
    const float* iw=(const float*)d_in[18], *ib=(const float*)d_in[19];
    const float* ow=(const float*)d_in[20], *ob=(const float*)d_in[21];
    const float* g2=(const float*)d_in[22], *b2=(const float*)d_in[23];

    float* out  = (float*)d_out;
    float* adjo = out + (long)BNr*Hq;     // adj output region

    void* p;
    cudaGetSymbolAddress(&p, g_outs);   float* outs=(float*)p;
    cudaGetSymbolAddress(&p, g_output); float* outp=(float*)p;
    cudaGetSymbolAddress(&p, g_bufA);   float* bA=(float*)p;
    cudaGetSymbolAddress(&p, g_bufB);   float* bB=(float*)p;
    cudaGetSymbolAddress(&p, g_bufC);   float* bC=(float*)p;
    cudaGetSymbolAddress(&p, g_scores); float* sc=(float*)p;
    cudaGetSymbolAddress(&p, g_scT);    float* scT=(float*)p;
    cudaGetSymbolAddress(&p, g_denom);  float* den=(float*)p;
    cudaGetSymbolAddress(&p, g_rmax);   float* rmax=(float*)p;
    cudaGetSymbolAddress(&p, g_rsum);   float* rsum=(float*)p;
    cudaGetSymbolAddress(&p, g_cmax);   float* cmax=(float*)p;
    cudaGetSymbolAddress(&p, g_csum);   float* csum=(float*)p;
    cudaGetSymbolAddress(&p, g_pmax);   float* pmax=(float*)p;
    cudaGetSymbolAddress(&p, g_psum);   float* psum=(float*)p;

    const long sNH = (long)Nq*Hq;
    const long sNN = (long)Nq*Nq;
    const float rscale = 1.0f/sqrtf((float)Hq);

    init_k<<<640,256>>>(text, outs, outp);
    adj_k<<<BNr,256>>>(adj1, adj2, adjo, den);

    for (int i=0;i<3;i++){
        const float *qwi=qw+i*Hq*Hq, *qbi=qb+i*Hq;
        const float *kwi=kw+i*Hq*Hq, *kbi=kb+i*Hq;
        const float *vwi=vw+i*Hq*Hq, *vbi=vb+i*Hq;
        const float *awi=aw+i*Hq*Hq, *abi=ab+i*Hq;
        const float *iwi=iw+i*Hq*Hq, *ibi=ib+i*Hq;
        const float *owi=ow+i*Hq*Hq, *obi=ob+i*Hq;
        const float *g1i=g1+i*Hq, *b1i=b1+i*Hq, *g2i=g2+i*Hq, *b2i=b2+i*Hq;

        // ---- BERT layer ----
        MG<0,0>(outs,qwi,bA, BNr,Hq,Hq, Hq,Hq,Hq, 0,0,0, 1, qbi,0,0,0,0.f);     // q
        MG<0,0>(outs,kwi,bB, BNr,Hq,Hq, Hq,Hq,Hq, 0,0,0, 1, kbi,0,0,0,0.f);     // k
        MG<0,0>(outs,vwi,bC, BNr,Hq,Hq, Hq,Hq,Hq, 0,0,0, 1, vbi,0,0,0,0.f);     // v
        MG<1,3>(bA,bB,sc, Nq,Nq,Hq, Hq,Hq,Nq, sNH,sNH,sNN, Bq, 0,0,0, tmask, rscale); // scores + keymask
        softmax_row_k<true><<<BNr,256>>>(sc, 0, 0);
        MG<0,0>(sc,bC,bA, Nq,Hq,Nq, Nq,Hq,Hq, sNN,sNH,sNH, Bq, 0,0,0,0,0.f);    // ctx
        MG<0,1>(bA,awi,bB, BNr,Hq,Hq, Hq,Hq,Hq, 0,0,0, 1, abi, outs, 0,0,0.f);  // pre-LN1
        ln_k<<<BNr,32>>>(bB, g1i, b1i, bC);                                      // attn
        MG<0,2>(bC,iwi,bA, BNr,Hq,Hq, Hq,Hq,Hq, 0,0,0, 1, ibi,0,0,0,0.f);       // inter (gelu)
        MG<0,1>(bA,owi,bB, BNr,Hq,Hq, Hq,Hq,Hq, 0,0,0, 1, obi, bC, 0,0,0.f);    // pre-LN2
        ln_k<<<BNr,32>>>(bB, g2i, b2i, outs);                                    // outs updated

        // ---- GCN propagation ----
        MG<0,0>(outp,gcn_w,bA, BNr,Hq,Hq, Hq,Hq,Hq, 0,0,0, 1, 0,0,0,0,0.f);     // teout
        MG<0,5>(adjo,bA,bB, Nq,Hq,Nq, Nq,Hq,Hq, sNN,sNH,sNH, Bq, 0, outp, den, 0, 0.f);
        { float* t_=outp; outp=bB; bB=t_; }                                      // output <- new

        // ---- self-alignment ----
        MG<0,0>(outs,mut_w,bA, BNr,Hq,Hq, Hq,Hq,Hq, 0,0,0, 1, 0,0,0,0,0.f);     // mo
        MG<1,4>(bA,outp,sc, Nq,Nq,Hq, Hq,Hq,Nq, sNH,sNH,sNN, Bq, 0,0,0, tmask, 0.f); // logit + pairmask
        softmax_row_k<false><<<BNr,256>>>(sc, rmax, rsum);
        colstats_part<<<dim3(BNr/256,NCH),256>>>(sc, pmax, psum);
        colstats_comb<<<BNr/256,256>>>(pmax, psum, cmax, csum);
        normalize_dual<<<dim3(Nq/32,Nq/32,Bq),256>>>(sc, scT, rmax, rsum, cmax, csum);
        MG<0,6>(sc, outp, bC, Nq,Hq,Nq, Nq,Hq,Hq, sNN,sNH,sNH, Bq, 0, outs, 0, tmask, 0.f); // new_outs
        MG<0,6>(scT, outs, bB, Nq,Hq,Nq, Nq,Hq,Hq, sNN,sNH,sNH, Bq, 0, outp, 0, tmask, 0.f); // new_output
        { float* t_=outs; outs=bC; bC=t_; }
        { float* t_=outp; outp=bB; bB=t_; }
    }

    cudaMemcpyAsync(out, outs, (size_t)BNr*Hq*sizeof(float), cudaMemcpyDeviceToDevice);
}